// round 2
// baseline (speedup 1.0000x reference)
#include <cuda_runtime.h>
#include <cstdint>

#define N_NODES 100000
#define N_EDGES 1600000
#define IN_DIM  128
#define HID     64
#define SZ      (N_NODES * HID)

// Scratch for segment-sum messages (device global: no allocs allowed).
__device__ float g_msgs[(size_t)N_NODES * HID];

// ---- packed f32x2 helpers (FFMA2: 2 FMA lanes per instruction) ----
#define FMA2(d, a, b, c) \
    asm("fma.rn.f32x2 %0, %1, %2, %3;" : "=l"(d) : "l"(a), "l"(b), "l"(c))

__device__ __forceinline__ unsigned long long pack2(float lo, float hi) {
    unsigned long long r;
    unsigned int l = __float_as_uint(lo), h = __float_as_uint(hi);
    asm("mov.b64 %0, {%1, %2};" : "=l"(r) : "r"(l), "r"(h));
    return r;
}

__device__ __forceinline__ float2 unpack2(unsigned long long v) {
    float2 f;
    unsigned int l, h;
    asm("mov.b64 {%0, %1}, %2;" : "=r"(l), "=r"(h) : "l"(v));
    f.x = __uint_as_float(l);
    f.y = __uint_as_float(h);
    return f;
}

// ============================================================================
// Kernel 1: h0 = relu(x @ Wi + bi), and zero g_msgs for the first scatter.
// 64 nodes/block, 256 threads. Thread = (jt in 0..7 -> 8 j's, nt in 0..31 -> 2 nodes).
// A tile padded to stride 132 (bank-conflict-free a-broadcast reads).
// ============================================================================
#define AS_IN 132
__global__ void __launch_bounds__(256) gemm_in_kernel(
    const float* __restrict__ x, const float* __restrict__ Wi,
    const float* __restrict__ bi, float* __restrict__ out)
{
    extern __shared__ float sm[];
    float* Ash = sm;                 // 64 x 132
    float* Wsh = sm + 64 * AS_IN;    // 128 x 64

    const int tid = threadIdx.x;
    const int nbase = blockIdx.x * 64;

    // Load Wi (128x64 = 2048 float4)
    for (int i = tid; i < 2048; i += 256)
        ((float4*)Wsh)[i] = ((const float4*)Wi)[i];

    // Load x tile (64 nodes x 128 = 2048 float4) into padded A
    for (int i = tid; i < 2048; i += 256) {
        int n = i >> 5, k4 = i & 31;
        int gn = nbase + n;
        float4 v = make_float4(0.f, 0.f, 0.f, 0.f);
        if (gn < N_NODES) v = ((const float4*)(x + (size_t)gn * IN_DIM))[k4];
        *(float4*)&Ash[n * AS_IN + k4 * 4] = v;
    }

    // Zero msgs for these nodes (first scatter input)
    for (int i = tid; i < 1024; i += 256) {
        int n = i >> 4, k4 = i & 15;
        int gn = nbase + n;
        if (gn < N_NODES)
            ((float4*)(g_msgs + (size_t)gn * HID))[k4] = make_float4(0.f, 0.f, 0.f, 0.f);
    }
    __syncthreads();

    const int jt = tid & 7, nt = tid >> 3;
    const int j0 = jt * 8;

    float4 b4a = ((const float4*)bi)[jt * 2];
    float4 b4b = ((const float4*)bi)[jt * 2 + 1];
    unsigned long long acc[2][4];
    #pragma unroll
    for (int m = 0; m < 2; m++) {
        acc[m][0] = pack2(b4a.x, b4a.y);
        acc[m][1] = pack2(b4a.z, b4a.w);
        acc[m][2] = pack2(b4b.x, b4b.y);
        acc[m][3] = pack2(b4b.z, b4b.w);
    }

    #pragma unroll 16
    for (int k = 0; k < IN_DIM; k++) {
        ulonglong2 w0 = *(const ulonglong2*)&Wsh[k * 64 + j0];
        ulonglong2 w1 = *(const ulonglong2*)&Wsh[k * 64 + j0 + 4];
        float a0 = Ash[nt * AS_IN + k];
        float a1 = Ash[(nt + 32) * AS_IN + k];
        unsigned long long ap0 = pack2(a0, a0);
        unsigned long long ap1 = pack2(a1, a1);
        FMA2(acc[0][0], ap0, w0.x, acc[0][0]);
        FMA2(acc[0][1], ap0, w0.y, acc[0][1]);
        FMA2(acc[0][2], ap0, w1.x, acc[0][2]);
        FMA2(acc[0][3], ap0, w1.y, acc[0][3]);
        FMA2(acc[1][0], ap1, w0.x, acc[1][0]);
        FMA2(acc[1][1], ap1, w0.y, acc[1][1]);
        FMA2(acc[1][2], ap1, w1.x, acc[1][2]);
        FMA2(acc[1][3], ap1, w1.y, acc[1][3]);
    }

    #pragma unroll
    for (int m = 0; m < 2; m++) {
        int gn = nbase + nt + m * 32;
        if (gn >= N_NODES) continue;
        float2 p0 = unpack2(acc[m][0]);
        float2 p1 = unpack2(acc[m][1]);
        float2 p2 = unpack2(acc[m][2]);
        float2 p3 = unpack2(acc[m][3]);
        float4 r0 = make_float4(fmaxf(p0.x, 0.f), fmaxf(p0.y, 0.f),
                                fmaxf(p1.x, 0.f), fmaxf(p1.y, 0.f));
        float4 r1 = make_float4(fmaxf(p2.x, 0.f), fmaxf(p2.y, 0.f),
                                fmaxf(p3.x, 0.f), fmaxf(p3.y, 0.f));
        float* op = out + (size_t)gn * HID + j0;
        *(float4*)op = r0;
        *(float4*)(op + 4) = r1;
    }
}

// ============================================================================
// Kernel 2: scatter — msgs[tgt] += h[src] * w, 16 threads per edge,
// one float4 per thread via red.global.add.v4.f32 (sm_90+ vector reduction).
// ============================================================================
__global__ void __launch_bounds__(256) scatter_kernel(
    const float* __restrict__ h, const int* __restrict__ src,
    const int* __restrict__ tgt, const float* __restrict__ ea)
{
    long long idx = (long long)blockIdx.x * 256 + threadIdx.x;
    int e = (int)(idx >> 4);
    if (e >= N_EDGES) return;
    int p = (int)(idx & 15);

    int s = src[e];
    int t = tgt[e];
    float we = ea[e];

    float4 v = ((const float4*)(h + (size_t)s * HID))[p];
    float vx = v.x * we, vy = v.y * we, vz = v.z * we, vw = v.w * we;
    float* dst = g_msgs + (size_t)t * HID + p * 4;
    asm volatile("red.global.add.v4.f32 [%0], {%1, %2, %3, %4};"
                 :: "l"(dst), "f"(vx), "f"(vy), "f"(vz), "f"(vw)
                 : "memory");
}

// ============================================================================
// Kernel 3: h_next = relu((h + msgs) @ W + b); zeros msgs after consuming it
// (so the next scatter sees a clean buffer — fused, no extra memset kernel).
// ============================================================================
#define AS_L 68
__global__ void __launch_bounds__(256) gemm_layer_kernel(
    const float* __restrict__ hin, const float* __restrict__ W,
    const float* __restrict__ b, float* __restrict__ out)
{
    __shared__ float Ash[64 * AS_L];   // 64 nodes x (64 + pad 4)
    __shared__ float Wsh[64 * 64];

    const int tid = threadIdx.x;
    const int nbase = blockIdx.x * 64;

    // Load W (64x64 = 1024 float4)
    for (int i = tid; i < 1024; i += 256)
        ((float4*)Wsh)[i] = ((const float4*)W)[i];

    // Load A = h + msgs (64 nodes x 64 = 1024 float4); zero msgs after reading
    for (int i = tid; i < 1024; i += 256) {
        int n = i >> 4, k4 = i & 15;
        int gn = nbase + n;
        float4 v = make_float4(0.f, 0.f, 0.f, 0.f);
        if (gn < N_NODES) {
            float4 hv = ((const float4*)(hin + (size_t)gn * HID))[k4];
            float4 mv = ((const float4*)(g_msgs + (size_t)gn * HID))[k4];
            v = make_float4(hv.x + mv.x, hv.y + mv.y, hv.z + mv.z, hv.w + mv.w);
            ((float4*)(g_msgs + (size_t)gn * HID))[k4] = make_float4(0.f, 0.f, 0.f, 0.f);
        }
        *(float4*)&Ash[n * AS_L + k4 * 4] = v;
    }
    __syncthreads();

    const int jt = tid & 7, nt = tid >> 3;
    const int j0 = jt * 8;

    float4 b4a = ((const float4*)b)[jt * 2];
    float4 b4b = ((const float4*)b)[jt * 2 + 1];
    unsigned long long acc[2][4];
    #pragma unroll
    for (int m = 0; m < 2; m++) {
        acc[m][0] = pack2(b4a.x, b4a.y);
        acc[m][1] = pack2(b4a.z, b4a.w);
        acc[m][2] = pack2(b4b.x, b4b.y);
        acc[m][3] = pack2(b4b.z, b4b.w);
    }

    #pragma unroll 16
    for (int k = 0; k < HID; k++) {
        ulonglong2 w0 = *(const ulonglong2*)&Wsh[k * 64 + j0];
        ulonglong2 w1 = *(const ulonglong2*)&Wsh[k * 64 + j0 + 4];
        float a0 = Ash[nt * AS_L + k];
        float a1 = Ash[(nt + 32) * AS_L + k];
        unsigned long long ap0 = pack2(a0, a0);
        unsigned long long ap1 = pack2(a1, a1);
        FMA2(acc[0][0], ap0, w0.x, acc[0][0]);
        FMA2(acc[0][1], ap0, w0.y, acc[0][1]);
        FMA2(acc[0][2], ap0, w1.x, acc[0][2]);
        FMA2(acc[0][3], ap0, w1.y, acc[0][3]);
        FMA2(acc[1][0], ap1, w0.x, acc[1][0]);
        FMA2(acc[1][1], ap1, w0.y, acc[1][1]);
        FMA2(acc[1][2], ap1, w1.x, acc[1][2]);
        FMA2(acc[1][3], ap1, w1.y, acc[1][3]);
    }

    #pragma unroll
    for (int m = 0; m < 2; m++) {
        int gn = nbase + nt + m * 32;
        if (gn >= N_NODES) continue;
        float2 p0 = unpack2(acc[m][0]);
        float2 p1 = unpack2(acc[m][1]);
        float2 p2 = unpack2(acc[m][2]);
        float2 p3 = unpack2(acc[m][3]);
        float4 r0 = make_float4(fmaxf(p0.x, 0.f), fmaxf(p0.y, 0.f),
                                fmaxf(p1.x, 0.f), fmaxf(p1.y, 0.f));
        float4 r1 = make_float4(fmaxf(p2.x, 0.f), fmaxf(p2.y, 0.f),
                                fmaxf(p3.x, 0.f), fmaxf(p3.y, 0.f));
        float* op = out + (size_t)gn * HID + j0;
        *(float4*)op = r0;
        *(float4*)(op + 4) = r1;
    }
}

// ============================================================================
// Launch: h0 = relu(xWi+bi) (+ zero msgs); then 3x (scatter, layer GEMM).
// Output layout: stack of 4 states, each [N_NODES, HID] fp32.
// ============================================================================
extern "C" void kernel_launch(void* const* d_in, const int* in_sizes, int n_in,
                              void* d_out, int out_size)
{
    const float* x  = (const float*)d_in[0];
    const int*   ei = (const int*)d_in[1];
    const float* ea = (const float*)d_in[2];
    const float* Wi = (const float*)d_in[3];
    const float* bi = (const float*)d_in[4];
    const float* Wl[3] = { (const float*)d_in[5], (const float*)d_in[7], (const float*)d_in[9] };
    const float* bl[3] = { (const float*)d_in[6], (const float*)d_in[8], (const float*)d_in[10] };
    float* out = (float*)d_out;

    const int* src = ei;
    const int* tgt = ei + N_EDGES;

    const int GEMM_BLOCKS = (N_NODES + 63) / 64;           // 1563
    const int SMEM_IN = (64 * AS_IN + IN_DIM * 64) * 4;    // 66560 B
    cudaFuncSetAttribute(gemm_in_kernel,
                         cudaFuncAttributeMaxDynamicSharedMemorySize, SMEM_IN);

    gemm_in_kernel<<<GEMM_BLOCKS, 256, SMEM_IN>>>(x, Wi, bi, out);

    const long long scatter_threads = (long long)N_EDGES * 16;
    const int SCATTER_BLOCKS = (int)((scatter_threads + 255) / 256);  // 100000

    for (int l = 0; l < 3; l++) {
        const float* hprev = out + (size_t)l * SZ;
        float* hnext = out + (size_t)(l + 1) * SZ;
        scatter_kernel<<<SCATTER_BLOCKS, 256>>>(hprev, src, tgt, ea);
        gemm_layer_kernel<<<GEMM_BLOCKS, 256>>>(hprev, Wl[l], bl[l], hnext);
    }
}

// round 3
// speedup vs baseline: 2.2516x; 2.2516x over previous
#include <cuda_runtime.h>
#include <cstdint>

#define N_NODES 100000
#define N_EDGES 1600000
#define IN_DIM  128
#define HID     64
#define SZ      (N_NODES * HID)
#define SCAN_B  1024
#define NSCAN   ((N_NODES + SCAN_B - 1) / SCAN_B)   // 98

typedef unsigned long long ull;

// CSR scratch (device globals: no allocs allowed)
__device__ int   g_cnt[N_NODES];
__device__ int   g_pos[N_NODES];
__device__ int   g_roff[N_NODES];    // block-partial exclusive prefix
__device__ int   g_bsum[NSCAN];
__device__ int   g_boff[NSCAN];
__device__ uint2 g_sw[N_EDGES];      // (src, w-bits) sorted by tgt

// ---- packed f32x2 helpers ----
#define FMA2(d, a, b, c) \
    asm("fma.rn.f32x2 %0, %1, %2, %3;" : "=l"(d) : "l"(a), "l"(b), "l"(c))

__device__ __forceinline__ ull pack2(float lo, float hi) {
    ull r;
    unsigned int l = __float_as_uint(lo), h = __float_as_uint(hi);
    asm("mov.b64 %0, {%1, %2};" : "=l"(r) : "r"(l), "r"(h));
    return r;
}
__device__ __forceinline__ float2 unpack2(ull v) {
    float2 f; unsigned int l, h;
    asm("mov.b64 {%0, %1}, %2;" : "=r"(l), "=r"(h) : "l"(v));
    f.x = __uint_as_float(l); f.y = __uint_as_float(h);
    return f;
}

// ============================================================================
// Kernel 1: h0 = relu(x @ Wi + bi).  128-node tile, 256 threads, thread tile
// 8 nodes x 4 cols, FMA2 accumulators (node pairs).  Also zeros g_cnt/g_pos.
// A stored k-major [128k][132 nodes] in smem (conflict-free: warp stores 32
// consecutive nodes at fixed k; 32B sector-aligned strided global reads).
// ============================================================================
#define NPAD 132
__global__ void __launch_bounds__(256) gemm_in_kernel(
    const float* __restrict__ x, const float* __restrict__ Wi,
    const float* __restrict__ bi, float* __restrict__ out)
{
    extern __shared__ float sm[];
    float* Ash = sm;                       // [128][132]
    float* Wsh = sm + IN_DIM * NPAD;       // [128][64]

    const int tid = threadIdx.x;
    const int nbase = blockIdx.x * 128;

    // zero CSR counters (independent work; hist runs after this kernel)
    int zi = blockIdx.x * 256 + tid;
    if (zi < N_NODES) { g_cnt[zi] = 0; g_pos[zi] = 0; }

    // load Wi (128x64 floats = 2048 float4)
    for (int i = tid; i < 2048; i += 256)
        ((float4*)Wsh)[i] = ((const float4*)Wi)[i];

    // load x tile transposed: i -> (k8, n); thread reads 32B (8 k's of node n)
    for (int i = tid; i < 2048; i += 256) {
        int k8 = i >> 7;           // 0..15
        int n  = i & 127;
        int gn = nbase + n;
        float4 v0 = make_float4(0.f,0.f,0.f,0.f), v1 = v0;
        if (gn < N_NODES) {
            const float4* xp = (const float4*)(x + (size_t)gn * IN_DIM + k8 * 8);
            v0 = __ldg(xp); v1 = __ldg(xp + 1);
        }
        int k = k8 * 8;
        Ash[(k+0)*NPAD + n] = v0.x; Ash[(k+1)*NPAD + n] = v0.y;
        Ash[(k+2)*NPAD + n] = v0.z; Ash[(k+3)*NPAD + n] = v0.w;
        Ash[(k+4)*NPAD + n] = v1.x; Ash[(k+5)*NPAD + n] = v1.y;
        Ash[(k+6)*NPAD + n] = v1.z; Ash[(k+7)*NPAD + n] = v1.w;
    }
    __syncthreads();

    const int r = tid >> 4;    // 0..15 -> nodes r*8..r*8+7
    const int c = tid & 15;    // 0..15 -> cols  c*4..c*4+3

    float4 bv = __ldg((const float4*)(bi + c * 4));
    ull acc[4][4];
    #pragma unroll
    for (int p = 0; p < 4; p++) {
        acc[p][0] = pack2(bv.x, bv.x); acc[p][1] = pack2(bv.y, bv.y);
        acc[p][2] = pack2(bv.z, bv.z); acc[p][3] = pack2(bv.w, bv.w);
    }

    #pragma unroll 8
    for (int k = 0; k < IN_DIM; k++) {
        const ulonglong2* ap = (const ulonglong2*)(Ash + k * NPAD + r * 8);
        ulonglong2 a01 = ap[0], a23 = ap[1];
        float4 wv = *(const float4*)(Wsh + k * HID + c * 4);
        ull w0 = pack2(wv.x, wv.x), w1 = pack2(wv.y, wv.y);
        ull w2 = pack2(wv.z, wv.z), w3 = pack2(wv.w, wv.w);
        ull ap_[4] = {a01.x, a01.y, a23.x, a23.y};
        #pragma unroll
        for (int p = 0; p < 4; p++) {
            FMA2(acc[p][0], ap_[p], w0, acc[p][0]);
            FMA2(acc[p][1], ap_[p], w1, acc[p][1]);
            FMA2(acc[p][2], ap_[p], w2, acc[p][2]);
            FMA2(acc[p][3], ap_[p], w3, acc[p][3]);
        }
    }

    #pragma unroll
    for (int p = 0; p < 4; p++) {
        float2 e0 = unpack2(acc[p][0]), e1 = unpack2(acc[p][1]);
        float2 e2 = unpack2(acc[p][2]), e3 = unpack2(acc[p][3]);
        int n0 = nbase + r * 8 + 2 * p;
        if (n0 < N_NODES) {
            float4 o = make_float4(fmaxf(e0.x,0.f), fmaxf(e1.x,0.f),
                                   fmaxf(e2.x,0.f), fmaxf(e3.x,0.f));
            *(float4*)(out + (size_t)n0 * HID + c * 4) = o;
        }
        if (n0 + 1 < N_NODES) {
            float4 o = make_float4(fmaxf(e0.y,0.f), fmaxf(e1.y,0.f),
                                   fmaxf(e2.y,0.f), fmaxf(e3.y,0.f));
            *(float4*)(out + (size_t)(n0+1) * HID + c * 4) = o;
        }
    }
}

// ============================================================================
// CSR build kernels
// ============================================================================
__global__ void hist_kernel(const int* __restrict__ tgt) {
    int e = blockIdx.x * 256 + threadIdx.x;
    if (e < N_EDGES) atomicAdd(&g_cnt[tgt[e]], 1);
}

__global__ void __launch_bounds__(SCAN_B) scanA_kernel() {
    __shared__ int s[SCAN_B];
    int t = threadIdx.x;
    int n = blockIdx.x * SCAN_B + t;
    int v = (n < N_NODES) ? g_cnt[n] : 0;
    s[t] = v;
    __syncthreads();
    #pragma unroll
    for (int d = 1; d < SCAN_B; d <<= 1) {
        int xv = (t >= d) ? s[t - d] : 0;
        __syncthreads();
        s[t] += xv;
        __syncthreads();
    }
    if (n < N_NODES) g_roff[n] = s[t] - v;           // block-partial exclusive
    if (t == SCAN_B - 1) g_bsum[blockIdx.x] = s[t];  // block total
}

__global__ void __launch_bounds__(128) scanB_kernel() {
    __shared__ int s[128];
    int t = threadIdx.x;
    int v = (t < NSCAN) ? g_bsum[t] : 0;
    s[t] = v;
    __syncthreads();
    #pragma unroll
    for (int d = 1; d < 128; d <<= 1) {
        int xv = (t >= d) ? s[t - d] : 0;
        __syncthreads();
        s[t] += xv;
        __syncthreads();
    }
    if (t < NSCAN) g_boff[t] = s[t] - v;             // exclusive
}

__global__ void fill_kernel(const int* __restrict__ src,
                            const int* __restrict__ tgt,
                            const float* __restrict__ ea) {
    int e = blockIdx.x * 256 + threadIdx.x;
    if (e >= N_EDGES) return;
    int t = tgt[e];
    int p = atomicAdd(&g_pos[t], 1);
    int base = g_roff[t] + g_boff[t >> 10];
    g_sw[base + p] = make_uint2((unsigned)src[e], __float_as_uint(ea[e]));
}

// ============================================================================
// Fused layer kernel: gather msgs via CSR (no atomics), A = h + msgs into
// k-major smem, then h_next = relu(A @ W + b).  128 nodes/block, 256 threads.
// Gather: 16 threads/node, float4/thread; h-row reads are fully coalesced
// (a 16-thread group reads one contiguous 256B row).
// ============================================================================
__global__ void __launch_bounds__(256) layer_kernel(
    const float* __restrict__ hin, const float* __restrict__ W,
    const float* __restrict__ b, float* __restrict__ out)
{
    extern __shared__ float sm[];
    float* Ash = sm;                   // [64][132]
    float* Wsh = sm + HID * NPAD;      // [64][64]

    const int tid = threadIdx.x;
    const int nbase = blockIdx.x * 128;

    for (int i = tid; i < 1024; i += 256)
        ((float4*)Wsh)[i] = ((const float4*)W)[i];

    const int grp = tid >> 4;   // 0..15 (node group)
    const int p   = tid & 15;   // float4 slot (k = p*4..p*4+3)

    for (int o = 0; o < 8; o++) {
        int ln = o * 16 + grp;
        int gn = nbase + ln;
        float4 acc = make_float4(0.f, 0.f, 0.f, 0.f);
        if (gn < N_NODES) {
            int ro = g_roff[gn] + g_boff[gn >> 10];
            int cn = g_cnt[gn];
            int i = 0;
            for (; i + 4 <= cn; i += 4) {
                uint2 s0 = g_sw[ro+i],   s1 = g_sw[ro+i+1];
                uint2 s2 = g_sw[ro+i+2], s3 = g_sw[ro+i+3];
                float4 v0 = __ldg((const float4*)(hin + (size_t)s0.x * HID) + p);
                float4 v1 = __ldg((const float4*)(hin + (size_t)s1.x * HID) + p);
                float4 v2 = __ldg((const float4*)(hin + (size_t)s2.x * HID) + p);
                float4 v3 = __ldg((const float4*)(hin + (size_t)s3.x * HID) + p);
                float w0 = __uint_as_float(s0.y), w1 = __uint_as_float(s1.y);
                float w2 = __uint_as_float(s2.y), w3 = __uint_as_float(s3.y);
                acc.x = fmaf(v0.x,w0, fmaf(v1.x,w1, fmaf(v2.x,w2, fmaf(v3.x,w3, acc.x))));
                acc.y = fmaf(v0.y,w0, fmaf(v1.y,w1, fmaf(v2.y,w2, fmaf(v3.y,w3, acc.y))));
                acc.z = fmaf(v0.z,w0, fmaf(v1.z,w1, fmaf(v2.z,w2, fmaf(v3.z,w3, acc.z))));
                acc.w = fmaf(v0.w,w0, fmaf(v1.w,w1, fmaf(v2.w,w2, fmaf(v3.w,w3, acc.w))));
            }
            for (; i < cn; i++) {
                uint2 sE = g_sw[ro + i];
                float4 v = __ldg((const float4*)(hin + (size_t)sE.x * HID) + p);
                float w = __uint_as_float(sE.y);
                acc.x = fmaf(v.x, w, acc.x); acc.y = fmaf(v.y, w, acc.y);
                acc.z = fmaf(v.z, w, acc.z); acc.w = fmaf(v.w, w, acc.w);
            }
            float4 hv = __ldg((const float4*)(hin + (size_t)gn * HID) + p);
            acc.x += hv.x; acc.y += hv.y; acc.z += hv.z; acc.w += hv.w;
        }
        int k0 = p * 4;
        Ash[(k0+0)*NPAD + ln] = acc.x;
        Ash[(k0+1)*NPAD + ln] = acc.y;
        Ash[(k0+2)*NPAD + ln] = acc.z;
        Ash[(k0+3)*NPAD + ln] = acc.w;
    }
    __syncthreads();

    const int r = tid >> 4;
    const int c = tid & 15;

    float4 bv = __ldg((const float4*)(b + c * 4));
    ull acc[4][4];
    #pragma unroll
    for (int q = 0; q < 4; q++) {
        acc[q][0] = pack2(bv.x, bv.x); acc[q][1] = pack2(bv.y, bv.y);
        acc[q][2] = pack2(bv.z, bv.z); acc[q][3] = pack2(bv.w, bv.w);
    }

    #pragma unroll 8
    for (int k = 0; k < HID; k++) {
        const ulonglong2* ap = (const ulonglong2*)(Ash + k * NPAD + r * 8);
        ulonglong2 a01 = ap[0], a23 = ap[1];
        float4 wv = *(const float4*)(Wsh + k * HID + c * 4);
        ull w0 = pack2(wv.x, wv.x), w1 = pack2(wv.y, wv.y);
        ull w2 = pack2(wv.z, wv.z), w3 = pack2(wv.w, wv.w);
        ull ap_[4] = {a01.x, a01.y, a23.x, a23.y};
        #pragma unroll
        for (int q = 0; q < 4; q++) {
            FMA2(acc[q][0], ap_[q], w0, acc[q][0]);
            FMA2(acc[q][1], ap_[q], w1, acc[q][1]);
            FMA2(acc[q][2], ap_[q], w2, acc[q][2]);
            FMA2(acc[q][3], ap_[q], w3, acc[q][3]);
        }
    }

    #pragma unroll
    for (int q = 0; q < 4; q++) {
        float2 e0 = unpack2(acc[q][0]), e1 = unpack2(acc[q][1]);
        float2 e2 = unpack2(acc[q][2]), e3 = unpack2(acc[q][3]);
        int n0 = nbase + r * 8 + 2 * q;
        if (n0 < N_NODES) {
            float4 ov = make_float4(fmaxf(e0.x,0.f), fmaxf(e1.x,0.f),
                                    fmaxf(e2.x,0.f), fmaxf(e3.x,0.f));
            *(float4*)(out + (size_t)n0 * HID + c * 4) = ov;
        }
        if (n0 + 1 < N_NODES) {
            float4 ov = make_float4(fmaxf(e0.y,0.f), fmaxf(e1.y,0.f),
                                    fmaxf(e2.y,0.f), fmaxf(e3.y,0.f));
            *(float4*)(out + (size_t)(n0+1) * HID + c * 4) = ov;
        }
    }
}

// ============================================================================
// Launch: gemm_in(+zero) | hist | scanA | scanB | fill | 3x fused layer.
// Layer 1 is launch #6 -> that's what ncu (-s 5 -c 1) will capture.
// ============================================================================
extern "C" void kernel_launch(void* const* d_in, const int* in_sizes, int n_in,
                              void* d_out, int out_size)
{
    const float* x  = (const float*)d_in[0];
    const int*   ei = (const int*)d_in[1];
    const float* ea = (const float*)d_in[2];
    const float* Wi = (const float*)d_in[3];
    const float* bi = (const float*)d_in[4];
    const float* Wl[3] = { (const float*)d_in[5], (const float*)d_in[7], (const float*)d_in[9] };
    const float* bl[3] = { (const float*)d_in[6], (const float*)d_in[8], (const float*)d_in[10] };
    float* out = (float*)d_out;

    const int* src = ei;
    const int* tgt = ei + N_EDGES;

    const int NODE_BLOCKS = (N_NODES + 127) / 128;              // 782
    const int EDGE_BLOCKS = (N_EDGES + 255) / 256;              // 6250
    const int SMEM_IN = (IN_DIM * NPAD + IN_DIM * HID) * 4;     // 100352
    const int SMEM_L  = (HID * NPAD + HID * HID) * 4;           // 50176

    cudaFuncSetAttribute(gemm_in_kernel,
                         cudaFuncAttributeMaxDynamicSharedMemorySize, SMEM_IN);
    cudaFuncSetAttribute(layer_kernel,
                         cudaFuncAttributeMaxDynamicSharedMemorySize, SMEM_L);

    gemm_in_kernel<<<NODE_BLOCKS, 256, SMEM_IN>>>(x, Wi, bi, out);   // 1
    hist_kernel<<<EDGE_BLOCKS, 256>>>(tgt);                          // 2
    scanA_kernel<<<NSCAN, SCAN_B>>>();                               // 3
    scanB_kernel<<<1, 128>>>();                                      // 4
    fill_kernel<<<EDGE_BLOCKS, 256>>>(src, tgt, ea);                 // 5

    for (int l = 0; l < 3; l++) {                                    // 6,7,8
        const float* hprev = out + (size_t)l * SZ;
        float* hnext = out + (size_t)(l + 1) * SZ;
        layer_kernel<<<NODE_BLOCKS, 256, SMEM_L>>>(hprev, Wl[l], bl[l], hnext);
    }
}

// round 5
// speedup vs baseline: 2.4711x; 1.0975x over previous
#include <cuda_runtime.h>
#include <cuda_fp16.h>
#include <cstdint>

#define N_NODES 100000
#define N_EDGES 1600000
#define IN_DIM  128
#define HID     64
#define SZ      (N_NODES * HID)
#define SCAN_B  1024
#define NSCAN   ((N_NODES + SCAN_B - 1) / SCAN_B)   // 98

typedef unsigned long long ull;

// Scratch (device globals: no allocs allowed)
__device__ int    g_cnt[N_NODES];
__device__ int    g_pos[N_NODES];
__device__ int    g_roff[N_NODES];
__device__ int    g_bsum[NSCAN];
__device__ int    g_boff[NSCAN];
__device__ uint2  g_sw[N_EDGES];          // (src, w-bits) grouped by tgt
// Double-buffered fp16 mirror of h: layer l READS buf[l&1], WRITES buf[(l+1)&1].
// (Single buffer raced in R4: same launch read remote rows while writing own.)
__device__ __half g_h16[2][SZ];

// ---- packed f32x2 helpers ----
#define FMA2(d, a, b, c) \
    asm("fma.rn.f32x2 %0, %1, %2, %3;" : "=l"(d) : "l"(a), "l"(b), "l"(c))

__device__ __forceinline__ ull pack2(float lo, float hi) {
    ull r;
    unsigned int l = __float_as_uint(lo), h = __float_as_uint(hi);
    asm("mov.b64 %0, {%1, %2};" : "=l"(r) : "r"(l), "r"(h));
    return r;
}
__device__ __forceinline__ float2 unpack2(ull v) {
    float2 f; unsigned int l, h;
    asm("mov.b64 {%0, %1}, %2;" : "=r"(l), "=r"(h) : "l"(v));
    f.x = __uint_as_float(l); f.y = __uint_as_float(h);
    return f;
}

// k-major A tile with XOR swizzle (conflict-free for the gather's 8-float
// per-thread column stores and the GEMM's 16B row reads).
#define NPAD 132
#define ASW(k)      ((((k) >> 3) & 7) << 2)
#define AIDX(k, n)  ((k) * NPAD + ((n) ^ ASW(k)))

// fp16x8 -> 8 fp32 FMA into acc
__device__ __forceinline__ void hfma8(uint4 v, float w, float* a) {
    float2 f;
    f = __half22float2(*(const __half2*)&v.x); a[0] = fmaf(f.x, w, a[0]); a[1] = fmaf(f.y, w, a[1]);
    f = __half22float2(*(const __half2*)&v.y); a[2] = fmaf(f.x, w, a[2]); a[3] = fmaf(f.y, w, a[3]);
    f = __half22float2(*(const __half2*)&v.z); a[4] = fmaf(f.x, w, a[4]); a[5] = fmaf(f.y, w, a[5]);
    f = __half22float2(*(const __half2*)&v.w); a[6] = fmaf(f.x, w, a[6]); a[7] = fmaf(f.y, w, a[7]);
}

__device__ __forceinline__ void store_h16(__half* dst, int gn, int c, float4 ov) {
    __half2 lo = __floats2half2_rn(ov.x, ov.y);
    __half2 hi = __floats2half2_rn(ov.z, ov.w);
    uint2 u;
    u.x = *reinterpret_cast<unsigned*>(&lo);
    u.y = *reinterpret_cast<unsigned*>(&hi);
    *reinterpret_cast<uint2*>((char*)dst + (size_t)gn * 128 + c * 8) = u;
}

// ============================================================================
// Kernel 0: zero CSR counters
// ============================================================================
__global__ void __launch_bounds__(1024) zero_kernel() {
    int i = blockIdx.x * 1024 + threadIdx.x;
    if (i < N_NODES) { g_cnt[i] = 0; g_pos[i] = 0; }
}

// ============================================================================
// Kernel 1: h0 = relu(x @ Wi + bi) (fp32 out + fp16 mirror buf0), with the
// CSR target histogram fused in (atomics overlap the FMA-bound GEMM).
// ============================================================================
__global__ void __launch_bounds__(256) gemm_in_kernel(
    const float* __restrict__ x, const float* __restrict__ Wi,
    const float* __restrict__ bi, const int* __restrict__ tgt,
    float* __restrict__ out)
{
    extern __shared__ float sm[];
    float* Ash = sm;                       // [128][132] swizzled
    float* Wsh = sm + IN_DIM * NPAD;       // [128][64]

    const int tid = threadIdx.x;
    const int nbase = blockIdx.x * 128;

    // fused histogram chunk (2048 edges/block, 782 blocks covers 1.6M)
    {
        int ebase = blockIdx.x * 2048;
        #pragma unroll
        for (int o = 0; o < 8; o++) {
            int e = ebase + o * 256 + tid;
            if (e < N_EDGES) atomicAdd(&g_cnt[tgt[e]], 1);
        }
    }

    for (int i = tid; i < 2048; i += 256)
        ((float4*)Wsh)[i] = ((const float4*)Wi)[i];

    for (int i = tid; i < 2048; i += 256) {
        int k8 = i >> 7;
        int n  = i & 127;
        int gn = nbase + n;
        float4 v0 = make_float4(0.f,0.f,0.f,0.f), v1 = v0;
        if (gn < N_NODES) {
            const float4* xp = (const float4*)(x + (size_t)gn * IN_DIM + k8 * 8);
            v0 = __ldg(xp); v1 = __ldg(xp + 1);
        }
        int k = k8 * 8;
        Ash[AIDX(k+0, n)] = v0.x; Ash[AIDX(k+1, n)] = v0.y;
        Ash[AIDX(k+2, n)] = v0.z; Ash[AIDX(k+3, n)] = v0.w;
        Ash[AIDX(k+4, n)] = v1.x; Ash[AIDX(k+5, n)] = v1.y;
        Ash[AIDX(k+6, n)] = v1.z; Ash[AIDX(k+7, n)] = v1.w;
    }
    __syncthreads();

    const int r = tid >> 4;
    const int c = tid & 15;

    float4 bv = __ldg((const float4*)(bi + c * 4));
    ull acc[4][4];
    #pragma unroll
    for (int p = 0; p < 4; p++) {
        acc[p][0] = pack2(bv.x, bv.x); acc[p][1] = pack2(bv.y, bv.y);
        acc[p][2] = pack2(bv.z, bv.z); acc[p][3] = pack2(bv.w, bv.w);
    }

    #pragma unroll 8
    for (int k = 0; k < IN_DIM; k++) {
        int q0 = (r * 8) ^ ASW(k);
        ulonglong2 aA = *(const ulonglong2*)&Ash[k * NPAD + q0];
        ulonglong2 aB = *(const ulonglong2*)&Ash[k * NPAD + (q0 ^ 4)];
        float4 wv = *(const float4*)(Wsh + k * HID + c * 4);
        ull w0 = pack2(wv.x, wv.x), w1 = pack2(wv.y, wv.y);
        ull w2 = pack2(wv.z, wv.z), w3 = pack2(wv.w, wv.w);
        ull ap_[4] = {aA.x, aA.y, aB.x, aB.y};
        #pragma unroll
        for (int p = 0; p < 4; p++) {
            FMA2(acc[p][0], ap_[p], w0, acc[p][0]);
            FMA2(acc[p][1], ap_[p], w1, acc[p][1]);
            FMA2(acc[p][2], ap_[p], w2, acc[p][2]);
            FMA2(acc[p][3], ap_[p], w3, acc[p][3]);
        }
    }

    #pragma unroll
    for (int p = 0; p < 4; p++) {
        float2 e0 = unpack2(acc[p][0]), e1 = unpack2(acc[p][1]);
        float2 e2 = unpack2(acc[p][2]), e3 = unpack2(acc[p][3]);
        int n0 = nbase + r * 8 + 2 * p;
        if (n0 < N_NODES) {
            float4 o = make_float4(fmaxf(e0.x,0.f), fmaxf(e1.x,0.f),
                                   fmaxf(e2.x,0.f), fmaxf(e3.x,0.f));
            *(float4*)(out + (size_t)n0 * HID + c * 4) = o;
            store_h16(g_h16[0], n0, c, o);
        }
        if (n0 + 1 < N_NODES) {
            float4 o = make_float4(fmaxf(e0.y,0.f), fmaxf(e1.y,0.f),
                                   fmaxf(e2.y,0.f), fmaxf(e3.y,0.f));
            *(float4*)(out + (size_t)(n0+1) * HID + c * 4) = o;
            store_h16(g_h16[0], n0 + 1, c, o);
        }
    }
}

// ============================================================================
// CSR scan + fill
// ============================================================================
__global__ void __launch_bounds__(SCAN_B) scanA_kernel() {
    __shared__ int s[SCAN_B];
    int t = threadIdx.x;
    int n = blockIdx.x * SCAN_B + t;
    int v = (n < N_NODES) ? g_cnt[n] : 0;
    s[t] = v;
    __syncthreads();
    #pragma unroll
    for (int d = 1; d < SCAN_B; d <<= 1) {
        int xv = (t >= d) ? s[t - d] : 0;
        __syncthreads();
        s[t] += xv;
        __syncthreads();
    }
    if (n < N_NODES) g_roff[n] = s[t] - v;
    if (t == SCAN_B - 1) g_bsum[blockIdx.x] = s[t];
}

__global__ void __launch_bounds__(128) scanB_kernel() {
    __shared__ int s[128];
    int t = threadIdx.x;
    int v = (t < NSCAN) ? g_bsum[t] : 0;
    s[t] = v;
    __syncthreads();
    #pragma unroll
    for (int d = 1; d < 128; d <<= 1) {
        int xv = (t >= d) ? s[t - d] : 0;
        __syncthreads();
        s[t] += xv;
        __syncthreads();
    }
    if (t < NSCAN) g_boff[t] = s[t] - v;
}

__global__ void fill_kernel(const int* __restrict__ src,
                            const int* __restrict__ tgt,
                            const float* __restrict__ ea) {
    int e = blockIdx.x * 256 + threadIdx.x;
    if (e >= N_EDGES) return;
    int t = tgt[e];
    int p = atomicAdd(&g_pos[t], 1);
    int base = g_roff[t] + g_boff[t >> 10];
    g_sw[base + p] = make_uint2((unsigned)src[e], __float_as_uint(ea[e]));
}

// ============================================================================
// Fused layer: gather msgs from fp16 mirror (read buf), A = h(fp32) + msgs
// into swizzled k-major smem, h_next = relu(A @ W + b) -> fp32 out + fp16
// mirror (write buf != read buf, so no cross-block race).
// ============================================================================
__global__ void __launch_bounds__(256) layer_kernel(
    const float* __restrict__ hin, const float* __restrict__ W,
    const float* __restrict__ b, float* __restrict__ out, int lparity)
{
    extern __shared__ float sm[];
    float* Ash = sm;                   // [64][132] swizzled
    float* Wsh = sm + HID * NPAD;      // [64][64]

    const __half* h16r = g_h16[lparity];
    __half*       h16w = g_h16[lparity ^ 1];

    const int tid = threadIdx.x;
    const int nbase = blockIdx.x * 128;

    for (int i = tid; i < 1024; i += 256)
        ((float4*)Wsh)[i] = ((const float4*)W)[i];

    const int grp = tid >> 3;   // 0..31 node group
    const int p   = tid & 7;    // k-slot: k = p*8 .. p*8+7

    #pragma unroll
    for (int o = 0; o < 4; o++) {
        int ln = o * 32 + grp;
        int gn = nbase + ln;
        float a[8] = {0.f,0.f,0.f,0.f,0.f,0.f,0.f,0.f};
        if (gn < N_NODES) {
            int rs = g_roff[gn] + g_boff[gn >> 10];
            int cn = g_cnt[gn];
            const uint2* sw = g_sw + rs;
            const char* hb = (const char*)h16r + p * 16;
            int i = 0;
            for (; i + 4 <= cn; i += 4) {
                uint2 s0 = sw[i],   s1 = sw[i+1];
                uint2 s2 = sw[i+2], s3 = sw[i+3];
                uint4 v0 = __ldg((const uint4*)(hb + (size_t)s0.x * 128));
                uint4 v1 = __ldg((const uint4*)(hb + (size_t)s1.x * 128));
                uint4 v2 = __ldg((const uint4*)(hb + (size_t)s2.x * 128));
                uint4 v3 = __ldg((const uint4*)(hb + (size_t)s3.x * 128));
                hfma8(v0, __uint_as_float(s0.y), a);
                hfma8(v1, __uint_as_float(s1.y), a);
                hfma8(v2, __uint_as_float(s2.y), a);
                hfma8(v3, __uint_as_float(s3.y), a);
            }
            for (; i < cn; i++) {
                uint2 sE = sw[i];
                uint4 v = __ldg((const uint4*)(hb + (size_t)sE.x * 128));
                hfma8(v, __uint_as_float(sE.y), a);
            }
            // exact fp32 self-term
            const float4* hp = (const float4*)(hin + (size_t)gn * HID + p * 8);
            float4 h0 = hp[0], h1 = hp[1];
            a[0]+=h0.x; a[1]+=h0.y; a[2]+=h0.z; a[3]+=h0.w;
            a[4]+=h1.x; a[5]+=h1.y; a[6]+=h1.z; a[7]+=h1.w;
        }
        int k0 = p * 8;
        #pragma unroll
        for (int j = 0; j < 8; j++)
            Ash[AIDX(k0 + j, ln)] = a[j];
    }
    __syncthreads();

    const int r = tid >> 4;
    const int c = tid & 15;

    float4 bv = __ldg((const float4*)(b + c * 4));
    ull acc[4][4];
    #pragma unroll
    for (int q = 0; q < 4; q++) {
        acc[q][0] = pack2(bv.x, bv.x); acc[q][1] = pack2(bv.y, bv.y);
        acc[q][2] = pack2(bv.z, bv.z); acc[q][3] = pack2(bv.w, bv.w);
    }

    #pragma unroll 8
    for (int k = 0; k < HID; k++) {
        int q0 = (r * 8) ^ ASW(k);
        ulonglong2 aA = *(const ulonglong2*)&Ash[k * NPAD + q0];
        ulonglong2 aB = *(const ulonglong2*)&Ash[k * NPAD + (q0 ^ 4)];
        float4 wv = *(const float4*)(Wsh + k * HID + c * 4);
        ull w0 = pack2(wv.x, wv.x), w1 = pack2(wv.y, wv.y);
        ull w2 = pack2(wv.z, wv.z), w3 = pack2(wv.w, wv.w);
        ull ap_[4] = {aA.x, aA.y, aB.x, aB.y};
        #pragma unroll
        for (int q = 0; q < 4; q++) {
            FMA2(acc[q][0], ap_[q], w0, acc[q][0]);
            FMA2(acc[q][1], ap_[q], w1, acc[q][1]);
            FMA2(acc[q][2], ap_[q], w2, acc[q][2]);
            FMA2(acc[q][3], ap_[q], w3, acc[q][3]);
        }
    }

    #pragma unroll
    for (int q = 0; q < 4; q++) {
        float2 e0 = unpack2(acc[q][0]), e1 = unpack2(acc[q][1]);
        float2 e2 = unpack2(acc[q][2]), e3 = unpack2(acc[q][3]);
        int n0 = nbase + r * 8 + 2 * q;
        if (n0 < N_NODES) {
            float4 ov = make_float4(fmaxf(e0.x,0.f), fmaxf(e1.x,0.f),
                                    fmaxf(e2.x,0.f), fmaxf(e3.x,0.f));
            *(float4*)(out + (size_t)n0 * HID + c * 4) = ov;
            store_h16(h16w, n0, c, ov);
        }
        if (n0 + 1 < N_NODES) {
            float4 ov = make_float4(fmaxf(e0.y,0.f), fmaxf(e1.y,0.f),
                                    fmaxf(e2.y,0.f), fmaxf(e3.y,0.f));
            *(float4*)(out + (size_t)(n0+1) * HID + c * 4) = ov;
            store_h16(h16w, n0 + 1, c, ov);
        }
    }
}

// ============================================================================
// Launch sequence
// ============================================================================
extern "C" void kernel_launch(void* const* d_in, const int* in_sizes, int n_in,
                              void* d_out, int out_size)
{
    const float* x  = (const float*)d_in[0];
    const int*   ei = (const int*)d_in[1];
    const float* ea = (const float*)d_in[2];
    const float* Wi = (const float*)d_in[3];
    const float* bi = (const float*)d_in[4];
    const float* Wl[3] = { (const float*)d_in[5], (const float*)d_in[7], (const float*)d_in[9] };
    const float* bl[3] = { (const float*)d_in[6], (const float*)d_in[8], (const float*)d_in[10] };
    float* out = (float*)d_out;

    const int* src = ei;
    const int* tgt = ei + N_EDGES;

    const int NODE_BLOCKS = (N_NODES + 127) / 128;              // 782
    const int EDGE_BLOCKS = (N_EDGES + 255) / 256;              // 6250
    const int SMEM_IN = (IN_DIM * NPAD + IN_DIM * HID) * 4;     // 100352
    const int SMEM_L  = (HID * NPAD + HID * HID) * 4;           // 50176

    cudaFuncSetAttribute(gemm_in_kernel,
                         cudaFuncAttributeMaxDynamicSharedMemorySize, SMEM_IN);
    cudaFuncSetAttribute(layer_kernel,
                         cudaFuncAttributeMaxDynamicSharedMemorySize, SMEM_L);

    zero_kernel<<<NSCAN, 1024>>>();                                    // 1
    gemm_in_kernel<<<NODE_BLOCKS, 256, SMEM_IN>>>(x, Wi, bi, tgt, out);// 2 (+hist)
    scanA_kernel<<<NSCAN, SCAN_B>>>();                                 // 3
    scanB_kernel<<<1, 128>>>();                                        // 4
    fill_kernel<<<EDGE_BLOCKS, 256>>>(src, tgt, ea);                   // 5

    for (int l = 0; l < 3; l++) {                                      // 6,7,8
        const float* hprev = out + (size_t)l * SZ;
        float* hnext = out + (size_t)(l + 1) * SZ;
        layer_kernel<<<NODE_BLOCKS, 256, SMEM_L>>>(hprev, Wl[l], bl[l],
                                                   hnext, l & 1);
    }
}